// round 4
// baseline (speedup 1.0000x reference)
#include <cuda_runtime.h>
#include <cuda_bf16.h>
#include <math.h>

#define NV    6144
#define HV    4
#define EPSV  1e-7f
#define MINV  1e-15f
#define NSEG  32
#define SEGR  192
#define CAP   24
#define AST   68
#define WLN   320

// ---------------- scratch ----------------
__device__ int   g_cnt[NV * NSEG];
__device__ int   g_nbr[(size_t)NV * NSEG * CAP];
__device__ float g_att[(size_t)HV * NV * AST];   // [0..63]=y, [64]=t
__device__ float g_pv [(size_t)HV * NV * AST];   // [0..63]=pv, [64]=lambda
__device__ float g_uT [(size_t)HV * 64 * NV];    // feature-major logmap vectors
__device__ float g_pcT[(size_t)256 * NV];        // feature-major poincare (raw, then scaled)
__device__ float g_osqP[8 * NV];                 // partial osq [osel*4+h][node]
__device__ float g_pre[(size_t)NV * WLN];
__device__ float g_WlP[256 * WLN];               // W_lin^T padded (zeros beyond 260)

// ---------------- helpers ----------------
__device__ __forceinline__ float wred(float v) {
#pragma unroll
    for (int o = 16; o; o >>= 1) v += __shfl_xor_sync(0xffffffffu, v, o);
    return v;
}
__device__ __forceinline__ float acoshr(float z) {
    float t = fmaxf(z * z - 1.0f, 0.0f);
    return logf(z + sqrtf(t));
}

// ---------------- K1: neighbor lists + W_lin transpose ----------------
__global__ __launch_bounds__(256) void k_build(const float* __restrict__ adj,
                                               const float* __restrict__ Wl) {
    if (blockIdx.y == NSEG) {
        for (int e = blockIdx.x * 256 + threadIdx.x; e < 256 * 260; e += 24 * 256) {
            int kk = e / 260, n = e % 260;
            g_WlP[(size_t)kk * WLN + n] = Wl[n * 257 + kk + 1];
        }
        return;
    }
    int c   = blockIdx.x * 256 + threadIdx.x;
    int seg = blockIdx.y;
    int cnt = 0;
    size_t base = ((size_t)c * NSEG + seg) * CAP;
    int j0 = seg * SEGR;
    for (int r = 0; r < SEGR; r += 8) {
        float v[8];
#pragma unroll
        for (int u = 0; u < 8; u++) v[u] = adj[(size_t)(j0 + r + u) * NV + c];
#pragma unroll
        for (int u = 0; u < 8; u++) {
            if (v[u] > 0.01f) {
                if (cnt < CAP) g_nbr[base + cnt] = j0 + r + u;
                cnt++;
            }
        }
    }
    g_cnt[c * NSEG + seg] = (cnt < CAP) ? cnt : CAP;
}

// ---------------- K2: hyp_linear att/data; 256 thr, 2 lanes per node --------
#define FSU  0                       // 128*65 = 8320
#define FSW  8320                    // 64*64  = 4096
#define FSO  12416                   // 64*133 = 8512
#define FST  20928                   // 384
#define SMEM_FEAT ((20928 + 384) * 4)

__global__ __launch_bounds__(256) void k_feat(const float* __restrict__ x,
                                              const float* __restrict__ Wa,
                                              const float* __restrict__ Wd) {
    extern __shared__ float sm[];
    float*  su  = sm + FSU;
    float*  sW  = sm + FSW;
    float4* sW4 = (float4*)sW;
    float*  so  = sm + FSO;
    float*  st  = sm + FST;
    int t = threadIdx.x, w = t >> 5, l = t & 31;
    int ln = t >> 1, half = t & 1;
    int m = blockIdx.y, h = m & 3;
    const float* W = (m < 4) ? (Wa + h * 4225) : (Wd + h * 4225);
    int nb = blockIdx.x * 128;

    for (int e = t; e < 128 * 65; e += 256) su[e] = x[(size_t)nb * 65 + e];
    for (int e = t; e < 64 * 64; e += 256) {
        int oo = e >> 6, c = e & 63;
        sW[e] = W[(oo + 1) * 65 + 1 + c];
    }
    __syncthreads();

    float u[32];
    float x0 = su[ln * 65];
    float q = 0.f;
#pragma unroll
    for (int c = 0; c < 32; c++) {
        u[c] = su[ln * 65 + 1 + half * 32 + c];
        q += u[c] * u[c];
    }
    float nsq = q + __shfl_xor_sync(0xffffffffu, q, 1);
    float scale = acoshr(fmaxf(x0, 1.0f + EPSV)) / fmaxf(sqrtf(nsq), MINV);
#pragma unroll
    for (int c = 0; c < 32; c++) u[c] *= scale;

    float osq = 0.f;
    for (int oo = 0; oo < 64; oo++) {
        float a0 = 0.f, a1 = 0.f, a2 = 0.f, a3 = 0.f;
#pragma unroll
        for (int c4 = 0; c4 < 8; c4++) {
            float4 wv = sW4[oo * 16 + half * 8 + c4];
            a0 += wv.x * u[4 * c4];
            a1 += wv.y * u[4 * c4 + 1];
            a2 += wv.z * u[4 * c4 + 2];
            a3 += wv.w * u[4 * c4 + 3];
        }
        float part = (a0 + a1) + (a2 + a3);
        float full = part + __shfl_xor_sync(0xffffffffu, part, 1);
        if (half == 0) so[oo * 133 + ln] = full;
        osq += full * full;
    }

    float n2 = fmaxf(sqrtf(osq), MINV);
    float shv = sinhf(n2) / n2;
    float ysq = shv * shv * osq;
    float tv = sqrtf(1.0f + ysq);
    if (half == 0) {
        st[ln] = shv; st[128 + ln] = tv;
        if (m >= 4) {
            float tp1 = tv + 1.0f;
            float pvsq = ysq / (tp1 * tp1);
            st[256 + ln] = 2.0f / fmaxf(1.0f - pvsq, MINV);
        }
    }
    __syncthreads();

    float* dst = (m < 4) ? g_att : g_pv;
    for (int n = 0; n < 16; n++) {
        int idx2 = w * 16 + n;
        int nd = nb + idx2;
        float* R = dst + ((size_t)(h * NV) + nd) * AST;
        float shn = st[idx2];
        float y1 = shn * so[l * 133 + idx2];
        float y2 = shn * so[(l + 32) * 133 + idx2];
        if (m < 4) {
            R[l] = y1; R[l + 32] = y2;
            if (l == 0) R[64] = st[128 + idx2];
        } else {
            float inv = 1.0f / (st[128 + idx2] + 1.0f);
            R[l] = y1 * inv; R[l + 32] = y2 * inv;
            if (l == 0) R[64] = st[256 + idx2];
        }
    }
}

// ---------------- K3: sparse attention + mobius -> g_uT ----------------
__global__ __launch_bounds__(128) void k_attn(void) {
    int i = blockIdx.x;
    int w = threadIdx.x >> 5, l = threadIdx.x & 31;
    int h = w;
    int s = l & 7, g = l >> 3;
    __shared__ int slist[800];
    __shared__ int stot;

    if (threadIdx.x < 32) {
        int c = g_cnt[i * NSEG + l];
        int sc = c;
#pragma unroll
        for (int o = 1; o < 32; o <<= 1) {
            int v = __shfl_up_sync(0xffffffffu, sc, o);
            if (l >= o) sc += v;
        }
        int off = sc - c;
        const int* lst = g_nbr + ((size_t)i * NSEG + l) * CAP;
        for (int k = 0; k < c; k++) slist[off + k] = lst[k];
        if (l == 31) stot = sc;
    }
    __syncthreads();
    int nk = stot;
    int nk4 = (nk + 3) & ~3;
    if (threadIdx.x < nk4 - nk) slist[nk + threadIdx.x] = slist[0];
    __syncthreads();

    const float* Ai = g_att + ((size_t)(h * NV) + i) * AST;
    float4 a0 = *(const float4*)(Ai + 8 * s);
    float4 a1 = *(const float4*)(Ai + 8 * s + 4);
    float ai0 = Ai[64];

    float T1 = 0.f, T2 = 0.f, U = 0.f, Q = 0.f;
    for (int kc = 0; kc < nk4; kc += 4) {
        int j = slist[kc + g];
        const float* Aj = g_att + ((size_t)(h * NV) + j) * AST;
        float4 b0 = *(const float4*)(Aj + 8 * s);
        float4 b1 = *(const float4*)(Aj + 8 * s + 4);
        float aj0 = Aj[64];
        float part = a0.x * b0.x + a0.y * b0.y + a0.z * b0.z + a0.w * b0.w
                   + a1.x * b1.x + a1.y * b1.y + a1.z * b1.z + a1.w * b1.w;
#pragma unroll
        for (int o = 4; o; o >>= 1) part += __shfl_xor_sync(0xffffffffu, part, o);
        float th = fmaxf(ai0 * aj0 - part, 1.0f + EPSV);
        float ar = acoshr(th);
        float S = fminf(ar * ar, 50.0f);
        if (kc + g >= nk) S = 0.0f;
#pragma unroll
        for (int gg = 0; gg < 4; gg++) {
            float Sg = __shfl_sync(0xffffffffu, S, gg * 8 + s);
            int jg = slist[kc + gg];
            const float* Pj = g_pv + ((size_t)(h * NV) + jg) * AST;
            float lam = Pj[64];
            float slg = Sg * lam;
            T1 += slg * Pj[l];
            T2 += slg * Pj[l + 32];
            U  += Sg * (lam - 1.0f);
            Q  += Sg * Sg;
        }
    }

    float nrm = fmaxf(sqrtf(Q), 1e-12f);
    float den = fmaxf(U / nrm, MINV);
    float v1 = (-T1 / nrm) / den, v2 = (-T2 / nrm) / den;
    float nvsq = wred(v1 * v1 + v2 * v2);
    float nv = fmaxf(sqrtf(nvsq), MINV);
    float ncl = fminf(nv, 1.0f - EPSV);
    float f = tanhf(0.5f * atanhf(ncl)) / nv;
    float m1 = f * v1, m2 = f * v2;
    float s2 = f * f * nvsq;
    float dd = fmaxf(1.0f - s2, MINV);
    float hb0 = (1.0f + s2) / dd;
    float nyy = fmaxf(2.0f * sqrtf(s2) / dd, MINV);
    float sc2 = acoshr(fmaxf(hb0, 1.0f + EPSV)) * (2.0f / dd) / nyy;
    g_uT[(size_t)(h * 64 + l) * NV + i]      = sc2 * m1;
    g_uT[(size_t)(h * 64 + l + 32) * NV + i] = sc2 * m2;
}

// ---------------- K4: Wo matvec, coalesced, raw outputs -> g_pcT --------------
__global__ __launch_bounds__(128) void k_post1(const float* __restrict__ Wo) {
    __shared__ float sW[64 * 64];
    float4* sW4 = (float4*)sW;
    int t = threadIdx.x;
    int h = blockIdx.y, osel = blockIdx.z;
    int node = blockIdx.x * 128 + t;

    for (int e = t; e < 64 * 64; e += 128) {
        int oo = e >> 6, c = e & 63;
        sW[e] = Wo[h * 4225 + (oo + 1) * 65 + 1 + c];
    }
    __syncthreads();

    float u[64];
#pragma unroll
    for (int c = 0; c < 64; c++) u[c] = g_uT[(size_t)(h * 64 + c) * NV + node];

    float osq = 0.f;
    for (int o2 = 0; o2 < 32; o2++) {
        int oo = osel * 32 + o2;
        float a0 = 0.f, a1 = 0.f, a2 = 0.f, a3 = 0.f;
#pragma unroll
        for (int c4 = 0; c4 < 16; c4++) {
            float4 wv = sW4[oo * 16 + c4];
            a0 += wv.x * u[4 * c4];
            a1 += wv.y * u[4 * c4 + 1];
            a2 += wv.z * u[4 * c4 + 2];
            a3 += wv.w * u[4 * c4 + 3];
        }
        float ov = (a0 + a1) + (a2 + a3);
        g_pcT[(size_t)(h * 64 + oo) * NV + node] = ov;
        osq += ov * ov;
    }
    g_osqP[(osel * 4 + h) * NV + node] = osq;
}

// ---------------- K5: per-node scales; scale g_pcT in place ----------------
__global__ __launch_bounds__(256) void k_scal2(void) {
    int node = blockIdx.x * 256 + threadIdx.x;
    float as[HV];
    float ssum = 0.f;
    float osqv[HV];
#pragma unroll
    for (int h = 0; h < HV; h++) {
        float osq = g_osqP[h * NV + node] + g_osqP[(4 + h) * NV + node];
        osqv[h] = osq;
        float n2 = fmaxf(sqrtf(osq), MINV);
        float sh = sinhf(n2) / n2;
        float tv = sqrtf(1.0f + sh * sh * osq);
        float cn = sh / (tv + 1.0f);
        as[h] = cn;
        ssum += cn * cn * osq;
    }
    float dd = fmaxf(1.0f - ssum, MINV);
    float hb0 = (1.0f + ssum) / dd;
    float nyy = fmaxf(2.0f * sqrtf(ssum) / dd, MINV);
    float srow = acoshr(fmaxf(hb0, 1.0f + EPSV)) * (2.0f / dd) / nyy;
#pragma unroll
    for (int h = 0; h < HV; h++) as[h] *= srow;
    (void)osqv;
#pragma unroll
    for (int h = 0; h < HV; h++)
        for (int o = 0; o < 64; o++) {
            size_t idx = (size_t)(h * 64 + o) * NV + node;
            g_pcT[idx] *= as[h];
        }
}

// ---------------- K6: SGEMM 64x64x16, A from feature-major g_pcT -------------
__global__ __launch_bounds__(256) void k_lin(void) {
    __shared__ float As[16][68];
    __shared__ float Bs[16][64];
    int t = threadIdx.x;
    int i0 = blockIdx.x * 64, n0 = blockIdx.y * 64;
    int tx = t & 15, ty = t >> 4;
    int ak = t >> 4, an4 = t & 15;
    int bk = t >> 4, bn4 = t & 15;
    float acc[4][4];
#pragma unroll
    for (int i = 0; i < 4; i++)
#pragma unroll
        for (int j = 0; j < 4; j++) acc[i][j] = 0.f;

    for (int k0 = 0; k0 < 256; k0 += 16) {
        __syncthreads();
        *(float4*)&As[ak][an4 * 4] =
            *(const float4*)&g_pcT[(size_t)(k0 + ak) * NV + i0 + an4 * 4];
        *(float4*)&Bs[bk][bn4 * 4] =
            *(const float4*)&g_WlP[(size_t)(k0 + bk) * WLN + n0 + bn4 * 4];
        __syncthreads();
#pragma unroll
        for (int k = 0; k < 16; k++) {
            float4 a = *(const float4*)&As[k][ty * 4];
            float4 b = *(const float4*)&Bs[k][tx * 4];
            acc[0][0] += a.x * b.x; acc[0][1] += a.x * b.y; acc[0][2] += a.x * b.z; acc[0][3] += a.x * b.w;
            acc[1][0] += a.y * b.x; acc[1][1] += a.y * b.y; acc[1][2] += a.y * b.z; acc[1][3] += a.y * b.w;
            acc[2][0] += a.z * b.x; acc[2][1] += a.z * b.y; acc[2][2] += a.z * b.z; acc[2][3] += a.z * b.w;
            acc[3][0] += a.w * b.x; acc[3][1] += a.w * b.y; acc[3][2] += a.w * b.z; acc[3][3] += a.w * b.w;
        }
    }
#pragma unroll
    for (int i = 0; i < 4; i++) {
        float4 v = make_float4(acc[i][0], acc[i][1], acc[i][2], acc[i][3]);
        *(float4*)&g_pre[(size_t)(i0 + ty * 4 + i) * WLN + n0 + tx * 4] = v;
    }
}

// ---------------- K7: final expmap0 + hyp_proj ----------------
__global__ __launch_bounds__(256) void k_final(float* __restrict__ out) {
    int w = threadIdx.x >> 5, l = threadIdx.x & 31;
    int row = blockIdx.x * 8 + w;
    float v[8], q = 0.f;
#pragma unroll
    for (int k = 0; k < 8; k++) {
        v[k] = g_pre[(size_t)row * WLN + k * 32 + l];
        if (!(k == 0 && l == 0)) q += v[k] * v[k];
    }
    float t4 = 0.f;
    if (l < 4) { t4 = g_pre[(size_t)row * WLN + 256 + l]; q += t4 * t4; }
    q = wred(q);
    float n2 = fmaxf(sqrtf(q), MINV);
    float sh = sinhf(n2) / n2;
    float tv = sqrtf(1.0f + sh * sh * q);
#pragma unroll
    for (int k = 0; k < 8; k++) {
        float o = (k == 0 && l == 0) ? tv : sh * v[k];
        out[(size_t)row * 260 + k * 32 + l] = o;
    }
    if (l < 4) out[(size_t)row * 260 + 256 + l] = sh * t4;
}

// ---------------- launch ----------------
extern "C" void kernel_launch(void* const* d_in, const int* in_sizes, int n_in,
                              void* d_out, int out_size) {
    const float* x     = (const float*)d_in[0];
    const float* adj   = (const float*)d_in[1];
    const float* W_att = (const float*)d_in[2];
    const float* W_dat = (const float*)d_in[3];
    const float* W_out = (const float*)d_in[4];
    const float* W_lin = (const float*)d_in[5];
    float* out = (float*)d_out;

    cudaFuncSetAttribute(k_feat, cudaFuncAttributeMaxDynamicSharedMemorySize, SMEM_FEAT);

    k_build<<<dim3(NV / 256, NSEG + 1), 256>>>(adj, W_lin);
    k_feat<<<dim3(NV / 128, 8), 256, SMEM_FEAT>>>(x, W_att, W_dat);
    k_attn<<<NV, 128>>>();
    k_post1<<<dim3(NV / 128, HV, 2), 128>>>(W_out);
    k_scal2<<<NV / 256, 256>>>();
    k_lin<<<dim3(NV / 64, 5), 256>>>();
    k_final<<<NV / 8, 256>>>(out);
}

// round 5
// speedup vs baseline: 1.1365x; 1.1365x over previous
#include <cuda_runtime.h>
#include <cuda_bf16.h>
#include <math.h>

#define NV    6144
#define HV    4
#define EPSV  1e-7f
#define MINV  1e-15f
#define NSEG  32
#define SEGR  192
#define CAP   24
#define AST   68
#define WLN   320

// ---------------- scratch ----------------
__device__ int   g_cnt[NV * NSEG];
__device__ int   g_nbr[(size_t)NV * NSEG * CAP];
__device__ float g_att[(size_t)HV * NV * AST];   // [0..63]=y, [64]=t
__device__ float g_dat[(size_t)HV * NV * AST];   // [0..63]=y, [64]=t   (data transform)
__device__ float g_u  [(size_t)HV * NV * 64];    // node-major mobius logmap vectors
__device__ float g_pcT[(size_t)256 * NV];        // feature-major RAW Wo outputs
__device__ float g_osq[HV * NV];                 // per-(head,node) |ov|^2
__device__ float g_as [HV * NV];                 // per-(head,node) fused scale
__device__ float g_pre[(size_t)NV * WLN];
__device__ float g_WlP[256 * WLN];               // W_lin^T padded (zeros beyond 260)

// ---------------- helpers ----------------
__device__ __forceinline__ float wred(float v) {
#pragma unroll
    for (int o = 16; o; o >>= 1) v += __shfl_xor_sync(0xffffffffu, v, o);
    return v;
}
__device__ __forceinline__ float acoshr(float z) {
    float t = fmaxf(z * z - 1.0f, 0.0f);
    return logf(z + sqrtf(t));
}

// ---------------- K1: neighbor lists + W_lin transpose ----------------
__global__ __launch_bounds__(256) void k_build(const float* __restrict__ adj,
                                               const float* __restrict__ Wl) {
    if (blockIdx.y == NSEG) {
        for (int e = blockIdx.x * 256 + threadIdx.x; e < 256 * 260; e += 24 * 256) {
            int kk = e / 260, n = e % 260;
            g_WlP[(size_t)kk * WLN + n] = Wl[n * 257 + kk + 1];
        }
        return;
    }
    int c   = blockIdx.x * 256 + threadIdx.x;
    int seg = blockIdx.y;
    int cnt = 0;
    size_t base = ((size_t)c * NSEG + seg) * CAP;
    int j0 = seg * SEGR;
    for (int r = 0; r < SEGR; r += 8) {
        float v[8];
#pragma unroll
        for (int u = 0; u < 8; u++) v[u] = adj[(size_t)(j0 + r + u) * NV + c];
#pragma unroll
        for (int u = 0; u < 8; u++) {
            if (v[u] > 0.01f) {
                if (cnt < CAP) g_nbr[base + cnt] = j0 + r + u;
                cnt++;
            }
        }
    }
    g_cnt[c * NSEG + seg] = (cnt < CAP) ? cnt : CAP;
}

// ---------------- K2: hyp_linear att/data -> (y, t) rows ----------------
// grid (48, 8): by = matrix (0..3 att, 4..7 data); block 128, warp-per-node.
#define SU_OFF  0                       // 128*65 = 8320
#define SW_OFF  8320                    // 64*64  = 4096
#define SO_OFF  12416                   // 4*64*33= 8448
#define ST_OFF  20864                   // 256
#define SMEM_FEAT ((20864 + 256) * 4)

__global__ __launch_bounds__(128) void k_feat(const float* __restrict__ x,
                                              const float* __restrict__ Wa,
                                              const float* __restrict__ Wd) {
    extern __shared__ float sm[];
    float*  su  = sm + SU_OFF;
    float*  sW  = sm + SW_OFF;
    float4* sW4 = (float4*)sW;
    float*  st  = sm + ST_OFF;
    int t = threadIdx.x, w = t >> 5, l = t & 31;
    int m = blockIdx.y, h = m & 3;
    const float* W = (m < 4) ? (Wa + h * 4225) : (Wd + h * 4225);
    int nb = blockIdx.x * 128;

    for (int e = t; e < 128 * 65; e += 128) su[e] = x[(size_t)nb * 65 + e];
    for (int e = t; e < 64 * 64; e += 128) {
        int oo = e >> 6, c = e & 63;
        sW[e] = W[(oo + 1) * 65 + 1 + c];
    }
    __syncthreads();

    // per-lane node: logmap0 into registers
    int ln = w * 32 + l;
    float u[64];
    float x0 = su[ln * 65];
    float q0 = 0.f, q1 = 0.f, q2 = 0.f, q3 = 0.f;
#pragma unroll
    for (int c = 0; c < 64; c += 4) {
        float a = su[ln * 65 + 1 + c], b = su[ln * 65 + 2 + c];
        float cc = su[ln * 65 + 3 + c], d = su[ln * 65 + 4 + c];
        u[c] = a; u[c + 1] = b; u[c + 2] = cc; u[c + 3] = d;
        q0 += a * a; q1 += b * b; q2 += cc * cc; q3 += d * d;
    }
    float nsq = (q0 + q1) + (q2 + q3);
    float ny = fmaxf(sqrtf(nsq), MINV);
    float scale = acoshr(fmaxf(x0, 1.0f + EPSV)) / ny;
#pragma unroll
    for (int c = 0; c < 64; c++) u[c] *= scale;

    float* so = sm + SO_OFF + w * 2112;
    float osq = 0.f;
    for (int oo = 0; oo < 64; oo++) {
        float a0 = 0.f, a1 = 0.f, a2 = 0.f, a3 = 0.f;
#pragma unroll
        for (int c4 = 0; c4 < 16; c4++) {
            float4 wv = sW4[oo * 16 + c4];
            a0 += wv.x * u[4 * c4];
            a1 += wv.y * u[4 * c4 + 1];
            a2 += wv.z * u[4 * c4 + 2];
            a3 += wv.w * u[4 * c4 + 3];
        }
        float ov = (a0 + a1) + (a2 + a3);
        so[oo * 33 + l] = ov;
        osq += ov * ov;
    }

    float n2 = fmaxf(sqrtf(osq), MINV);
    float shv = sinhf(n2) / n2;
    float tv = sqrtf(1.0f + shv * shv * osq);
    st[t] = shv; st[128 + t] = tv;
    __syncwarp();

    float* dst = (m < 4) ? g_att : g_dat;
    for (int n = 0; n < 32; n++) {
        int nd = nb + w * 32 + n;
        float* R = dst + ((size_t)(h * NV) + nd) * AST;
        float shn = st[w * 32 + n];
        R[l]      = shn * so[l * 33 + n];
        R[l + 32] = shn * so[(l + 32) * 33 + n];
        if (l == 0) R[64] = st[128 + w * 32 + n];
    }
}

// ---------------- K3: sparse attention + mobius -> g_u (node-major) ----------
__global__ __launch_bounds__(128) void k_attn(void) {
    int i = blockIdx.x;
    int w = threadIdx.x >> 5, l = threadIdx.x & 31;
    int h = w;
    int s = l & 7, g = l >> 3;
    __shared__ int slist[800];
    __shared__ int stot;

    if (threadIdx.x < 32) {
        int c = g_cnt[i * NSEG + l];
        int sc = c;
#pragma unroll
        for (int o = 1; o < 32; o <<= 1) {
            int v = __shfl_up_sync(0xffffffffu, sc, o);
            if (l >= o) sc += v;
        }
        int off = sc - c;
        const int* lst = g_nbr + ((size_t)i * NSEG + l) * CAP;
        for (int k = 0; k < c; k++) slist[off + k] = lst[k];
        if (l == 31) stot = sc;
    }
    __syncthreads();
    int nk = stot;
    int nk4 = (nk + 3) & ~3;
    if (threadIdx.x < nk4 - nk) slist[nk + threadIdx.x] = slist[0];
    __syncthreads();

    const float* Ai = g_att + ((size_t)(h * NV) + i) * AST;
    float4 a0 = *(const float4*)(Ai + 8 * s);
    float4 a1 = *(const float4*)(Ai + 8 * s + 4);
    float ai0 = Ai[64];

    float T1 = 0.f, T2 = 0.f, U = 0.f, Q = 0.f;
    for (int kc = 0; kc < nk4; kc += 4) {
        int j = slist[kc + g];
        const float* Aj = g_att + ((size_t)(h * NV) + j) * AST;
        float4 b0 = *(const float4*)(Aj + 8 * s);
        float4 b1 = *(const float4*)(Aj + 8 * s + 4);
        float aj0 = Aj[64];
        float part = a0.x * b0.x + a0.y * b0.y + a0.z * b0.z + a0.w * b0.w
                   + a1.x * b1.x + a1.y * b1.y + a1.z * b1.z + a1.w * b1.w;
#pragma unroll
        for (int o = 4; o; o >>= 1) part += __shfl_xor_sync(0xffffffffu, part, o);
        float th = fmaxf(ai0 * aj0 - part, 1.0f + EPSV);
        float ar = acoshr(th);
        float S = fminf(ar * ar, 50.0f);
        if (kc + g >= nk) S = 0.0f;
#pragma unroll
        for (int gg = 0; gg < 4; gg++) {
            float Sg = __shfl_sync(0xffffffffu, S, gg * 8 + s);
            int jg = slist[kc + gg];
            const float* Dj = g_dat + ((size_t)(h * NV) + jg) * AST;
            // lam*pv = y ; lam-1 = t  (hyperboloid identity)
            T1 += Sg * Dj[l];
            T2 += Sg * Dj[l + 32];
            U  += Sg * Dj[64];
            Q  += Sg * Sg;
        }
    }

    float nrm = fmaxf(sqrtf(Q), 1e-12f);
    float den = fmaxf(U / nrm, MINV);
    float v1 = (-T1 / nrm) / den, v2 = (-T2 / nrm) / den;
    float nvsq = wred(v1 * v1 + v2 * v2);
    float nv = fmaxf(sqrtf(nvsq), MINV);
    float ncl = fminf(nv, 1.0f - EPSV);
    float f = tanhf(0.5f * atanhf(ncl)) / nv;
    float m1 = f * v1, m2 = f * v2;
    float s2 = f * f * nvsq;
    float dd = fmaxf(1.0f - s2, MINV);
    float hb0 = (1.0f + s2) / dd;
    float nyy = fmaxf(2.0f * sqrtf(s2) / dd, MINV);
    float sc2 = acoshr(fmaxf(hb0, 1.0f + EPSV)) * (2.0f / dd) / nyy;
    float* Uo = g_u + ((size_t)(h * NV) + i) * 64;
    Uo[l]      = sc2 * m1;
    Uo[l + 32] = sc2 * m2;
}

// ---------------- K4: Wo matvec node-per-thread -> raw g_pcT + osq -----------
__global__ __launch_bounds__(128) void k_post1(const float* __restrict__ Wo) {
    __shared__ float sU[128 * 65];
    __shared__ float sW[64 * 64];
    float4* sW4 = (float4*)sW;
    int t = threadIdx.x;
    int h = blockIdx.y;
    int nb = blockIdx.x * 128;
    int node = nb + t;

    for (int e = t; e < 128 * 64; e += 128) {
        int n = e >> 6, c = e & 63;
        sU[n * 65 + c] = g_u[((size_t)(h * NV) + nb) * 64 + e];
    }
    for (int e = t; e < 64 * 64; e += 128) {
        int oo = e >> 6, c = e & 63;
        sW[e] = Wo[h * 4225 + (oo + 1) * 65 + 1 + c];
    }
    __syncthreads();

    float u[64];
#pragma unroll
    for (int c = 0; c < 64; c++) u[c] = sU[t * 65 + c];

    float osq = 0.f;
    for (int oo = 0; oo < 64; oo++) {
        float a0 = 0.f, a1 = 0.f, a2 = 0.f, a3 = 0.f;
#pragma unroll
        for (int c4 = 0; c4 < 16; c4++) {
            float4 wv = sW4[oo * 16 + c4];
            a0 += wv.x * u[4 * c4];
            a1 += wv.y * u[4 * c4 + 1];
            a2 += wv.z * u[4 * c4 + 2];
            a3 += wv.w * u[4 * c4 + 3];
        }
        float ov = (a0 + a1) + (a2 + a3);
        g_pcT[(size_t)(h * 64 + oo) * NV + node] = ov;
        osq += ov * ov;
    }
    g_osq[h * NV + node] = osq;
}

// ---------------- K5: fused per-(head,node) scale ----------------
__global__ __launch_bounds__(256) void k_scal(void) {
    int node = blockIdx.x * 256 + threadIdx.x;
    float cn[HV];
    float ssum = 0.f;
#pragma unroll
    for (int h = 0; h < HV; h++) {
        float osq = g_osq[h * NV + node];
        float n2 = fmaxf(sqrtf(osq), MINV);
        float sh = sinhf(n2) / n2;
        float tv = sqrtf(1.0f + sh * sh * osq);
        cn[h] = sh / (tv + 1.0f);
        ssum += cn[h] * cn[h] * osq;
    }
    float dd = fmaxf(1.0f - ssum, MINV);
    float hb0 = (1.0f + ssum) / dd;
    float nyy = fmaxf(2.0f * sqrtf(ssum) / dd, MINV);
    float srow = acoshr(fmaxf(hb0, 1.0f + EPSV)) * (2.0f / dd) / nyy;
#pragma unroll
    for (int h = 0; h < HV; h++) g_as[h * NV + node] = cn[h] * srow;
}

// ---------------- K6: SGEMM 64x64x16, scale fused on A load ------------------
__global__ __launch_bounds__(256) void k_lin(void) {
    __shared__ float As[16][68];
    __shared__ float Bs[16][64];
    __shared__ float sAS[4][64];
    int t = threadIdx.x;
    int i0 = blockIdx.x * 64, n0 = blockIdx.y * 64;
    int tx = t & 15, ty = t >> 4;
    int ak = t >> 4, an4 = t & 15;
    float acc[4][4];
#pragma unroll
    for (int i = 0; i < 4; i++)
#pragma unroll
        for (int j = 0; j < 4; j++) acc[i][j] = 0.f;

    {   // stage per-node/head scales: t in [0,256): h=t>>6, n=t&63
        int h = t >> 6, n = t & 63;
        sAS[h][n] = g_as[h * NV + i0 + n];
    }
    __syncthreads();

    for (int k0 = 0; k0 < 256; k0 += 16) {
        int hh = k0 >> 6;
        __syncthreads();
        float4 av = *(const float4*)&g_pcT[(size_t)(k0 + ak) * NV + i0 + an4 * 4];
        float4 sv = *(const float4*)&sAS[hh][an4 * 4];
        As[ak][an4 * 4 + 0] = av.x * sv.x;
        As[ak][an4 * 4 + 1] = av.y * sv.y;
        As[ak][an4 * 4 + 2] = av.z * sv.z;
        As[ak][an4 * 4 + 3] = av.w * sv.w;
        *(float4*)&Bs[ak][an4 * 4] =
            *(const float4*)&g_WlP[(size_t)(k0 + ak) * WLN + n0 + an4 * 4];
        __syncthreads();
#pragma unroll
        for (int k = 0; k < 16; k++) {
            float4 a = *(const float4*)&As[k][ty * 4];
            float4 b = *(const float4*)&Bs[k][tx * 4];
            acc[0][0] += a.x * b.x; acc[0][1] += a.x * b.y; acc[0][2] += a.x * b.z; acc[0][3] += a.x * b.w;
            acc[1][0] += a.y * b.x; acc[1][1] += a.y * b.y; acc[1][2] += a.y * b.z; acc[1][3] += a.y * b.w;
            acc[2][0] += a.z * b.x; acc[2][1] += a.z * b.y; acc[2][2] += a.z * b.z; acc[2][3] += a.z * b.w;
            acc[3][0] += a.w * b.x; acc[3][1] += a.w * b.y; acc[3][2] += a.w * b.z; acc[3][3] += a.w * b.w;
        }
    }
#pragma unroll
    for (int i = 0; i < 4; i++) {
        float4 v = make_float4(acc[i][0], acc[i][1], acc[i][2], acc[i][3]);
        *(float4*)&g_pre[(size_t)(i0 + ty * 4 + i) * WLN + n0 + tx * 4] = v;
    }
}

// ---------------- K7: final expmap0 + hyp_proj ----------------
__global__ __launch_bounds__(256) void k_final(float* __restrict__ out) {
    int w = threadIdx.x >> 5, l = threadIdx.x & 31;
    int row = blockIdx.x * 8 + w;
    float v[8], q = 0.f;
#pragma unroll
    for (int k = 0; k < 8; k++) {
        v[k] = g_pre[(size_t)row * WLN + k * 32 + l];
        if (!(k == 0 && l == 0)) q += v[k] * v[k];
    }
    float t4 = 0.f;
    if (l < 4) { t4 = g_pre[(size_t)row * WLN + 256 + l]; q += t4 * t4; }
    q = wred(q);
    float n2 = fmaxf(sqrtf(q), MINV);
    float sh = sinhf(n2) / n2;
    float tv = sqrtf(1.0f + sh * sh * q);
#pragma unroll
    for (int k = 0; k < 8; k++) {
        float o = (k == 0 && l == 0) ? tv : sh * v[k];
        out[(size_t)row * 260 + k * 32 + l] = o;
    }
    if (l < 4) out[(size_t)row * 260 + 256 + l] = sh * t4;
}

// ---------------- launch ----------------
extern "C" void kernel_launch(void* const* d_in, const int* in_sizes, int n_in,
                              void* d_out, int out_size) {
    const float* x     = (const float*)d_in[0];
    const float* adj   = (const float*)d_in[1];
    const float* W_att = (const float*)d_in[2];
    const float* W_dat = (const float*)d_in[3];
    const float* W_out = (const float*)d_in[4];
    const float* W_lin = (const float*)d_in[5];
    float* out = (float*)d_out;

    cudaFuncSetAttribute(k_feat, cudaFuncAttributeMaxDynamicSharedMemorySize, SMEM_FEAT);

    k_build<<<dim3(NV / 256, NSEG + 1), 256>>>(adj, W_lin);
    k_feat<<<dim3(NV / 128, 8), 128, SMEM_FEAT>>>(x, W_att, W_dat);
    k_attn<<<NV, 128>>>();
    k_post1<<<dim3(NV / 128, HV), 128>>>(W_out);
    k_scal<<<NV / 256, 256>>>();
    k_lin<<<dim3(NV / 64, 5), 256>>>();
    k_final<<<NV / 8, 256>>>(out);
}